// round 6
// baseline (speedup 1.0000x reference)
#include <cuda_runtime.h>
#include <cstdint>

// ---------------- problem constants (fixed by reference setup) ----------------
#define N_SRC0 100000
#define N_DST0 20000
#define N_DST1 4000
#define NEDGE0 500000
#define NEDGE1 100000
#define D_IN 128
#define D_H 256

// ---------------- scratch (device globals; no allocation allowed) -------------
__device__ float g_mean0[N_DST0 * D_IN];  // layer0 segment means
__device__ float g_h[N_DST0 * D_H];       // layer0 output (relu'd)
__device__ float g_mean1[N_DST1 * D_H];   // layer1 segment means
__device__ float g_out[N_DST1 * D_H];     // layer1 raw output (pre-softmax)

__device__ int g_cnt0[N_DST0];            // per-dst edge counts (layer0)
__device__ int g_rowptr0[N_DST0 + 1];
__device__ int g_cursor0[N_DST0];
__device__ int g_col0[NEDGE0];            // CSR column (src) ids
__device__ int g_cnt1[N_DST1];
__device__ int g_rowptr1[N_DST1 + 1];
__device__ int g_cursor1[N_DST1];
__device__ int g_col1[NEDGE1];

// ---------------- zero counts ----------------
__global__ void zero_cnt_kernel() {
    int i = blockIdx.x * blockDim.x + threadIdx.x;
    if (i < N_DST0) g_cnt0[i] = 0;
    if (i < N_DST1) g_cnt1[i] = 0;
}

// ---------------- CSR build: count, scan, fill -------------------------------
__global__ void count_kernel(const int* __restrict__ ei, int* __restrict__ cnt, int E) {
    int e = blockIdx.x * blockDim.x + threadIdx.x;
    if (e < E) atomicAdd(&cnt[ei[E + e]], 1);
}

// single-block sequential-chunk scan: rowptr[0..n] (exclusive) + cursor=rowptr
__global__ void scan_kernel(const int* __restrict__ cnt, int* __restrict__ rowptr,
                            int* __restrict__ cursor, int n) {
    __shared__ int buf[1024];
    __shared__ int carry;
    if (threadIdx.x == 0) carry = 0;
    __syncthreads();
    for (int base = 0; base < n; base += 1024) {
        int i = base + threadIdx.x;
        int v = (i < n) ? cnt[i] : 0;
        buf[threadIdx.x] = v;
        __syncthreads();
#pragma unroll
        for (int off = 1; off < 1024; off <<= 1) {
            int t = (threadIdx.x >= off) ? buf[threadIdx.x - off] : 0;
            __syncthreads();
            buf[threadIdx.x] += t;
            __syncthreads();
        }
        if (i < n) {
            int excl = carry + buf[threadIdx.x] - v;
            rowptr[i] = excl;
            cursor[i] = excl;
            if (i == n - 1) rowptr[n] = carry + buf[threadIdx.x];
        }
        __syncthreads();
        if (threadIdx.x == 0) carry += buf[1023];
        __syncthreads();
    }
}

__global__ void fill_kernel(const int* __restrict__ ei, int* __restrict__ cursor,
                            int* __restrict__ col, int E) {
    int e = blockIdx.x * blockDim.x + threadIdx.x;
    if (e < E) {
        int d = ei[E + e];
        int slot = atomicAdd(&cursor[d], 1);
        col[slot] = ei[e];   // src id
    }
}

// ---------------- dst-major aggregation (mean), no float atomics --------------
// layer0: D=128, one warp per dst, lane holds one float4
__global__ void agg0_kernel(const float* __restrict__ x) {
    int w = (blockIdx.x * blockDim.x + threadIdx.x) >> 5;
    int lane = threadIdx.x & 31;
    if (w >= N_DST0) return;
    int beg = g_rowptr0[w], end = g_rowptr0[w + 1];
    float4 acc = make_float4(0.f, 0.f, 0.f, 0.f);
    int e = beg;
    for (; e + 2 <= end; e += 2) {
        int s0 = g_col0[e], s1 = g_col0[e + 1];
        float4 v0 = ((const float4*)(x + (size_t)s0 * D_IN))[lane];
        float4 v1 = ((const float4*)(x + (size_t)s1 * D_IN))[lane];
        acc.x += v0.x; acc.y += v0.y; acc.z += v0.z; acc.w += v0.w;
        acc.x += v1.x; acc.y += v1.y; acc.z += v1.z; acc.w += v1.w;
    }
    if (e < end) {
        float4 v = ((const float4*)(x + (size_t)g_col0[e] * D_IN))[lane];
        acc.x += v.x; acc.y += v.y; acc.z += v.z; acc.w += v.w;
    }
    float s = 1.f / fmaxf((float)(end - beg), 1.f);
    acc.x *= s; acc.y *= s; acc.z *= s; acc.w *= s;
    ((float4*)(g_mean0 + (size_t)w * D_IN))[lane] = acc;
}

// layer1: D=256, one warp per dst, lane holds two float4s
__global__ void agg1_kernel() {
    int w = (blockIdx.x * blockDim.x + threadIdx.x) >> 5;
    int lane = threadIdx.x & 31;
    if (w >= N_DST1) return;
    int beg = g_rowptr1[w], end = g_rowptr1[w + 1];
    float4 a0 = make_float4(0.f, 0.f, 0.f, 0.f);
    float4 a1 = make_float4(0.f, 0.f, 0.f, 0.f);
    for (int e = beg; e < end; e++) {
        const float4* hs = (const float4*)(g_h + (size_t)g_col1[e] * D_H);
        float4 v0 = hs[lane];
        float4 v1 = hs[lane + 32];
        a0.x += v0.x; a0.y += v0.y; a0.z += v0.z; a0.w += v0.w;
        a1.x += v1.x; a1.y += v1.y; a1.z += v1.z; a1.w += v1.w;
    }
    float s = 1.f / fmaxf((float)(end - beg), 1.f);
    a0.x *= s; a0.y *= s; a0.z *= s; a0.w *= s;
    a1.x *= s; a1.y *= s; a1.z *= s; a1.w *= s;
    float4* op = (float4*)(g_mean1 + (size_t)w * D_H);
    op[lane] = a0;
    op[lane + 32] = a1;
}

// ---------------- dual-A GEMM: out = A1@W1 + A2@W2 + b  (opt relu) ------------
// 128x128x8 tile, 256 threads, 8x8 microtile, As transposed for float4 LDS.
#define BM 128
#define BN 128
#define BK 8
__global__ void __launch_bounds__(256, 2)
gemm_dual_kernel(const float* __restrict__ A1,
                 const float* __restrict__ A2,
                 const float* __restrict__ W1, const float* __restrict__ W2,
                 const float* __restrict__ bias,
                 float* __restrict__ out, int M, int K, int do_relu) {
    __shared__ float As[BK][BM];     // transposed A tile
    __shared__ float Bs[BK][BN];

    const int tid = threadIdx.x;
    const int tx = tid & 15;         // 0..15 -> 8 cols each
    const int ty = tid >> 4;         // 0..15 -> 8 rows each
    const int bm = blockIdx.y * BM;
    const int bn = blockIdx.x * BN;

    const int a_row = tid >> 1;            // 0..127
    const int a_kc  = (tid & 1) * 4;       // 0 or 4
    const int b_kr  = tid >> 5;            // 0..7
    const int b_col = (tid & 31) * 4;      // 0..124

    float acc[8][8];
#pragma unroll
    for (int i = 0; i < 8; i++)
#pragma unroll
        for (int j = 0; j < 8; j++) acc[i][j] = 0.f;

    for (int pass = 0; pass < 2; pass++) {
        const float* __restrict__ A = pass ? A2 : A1;
        const float* __restrict__ W = pass ? W2 : W1;
        const int gr = bm + a_row;

        for (int k0 = 0; k0 < K; k0 += BK) {
            float4 av = make_float4(0.f, 0.f, 0.f, 0.f);
            if (gr < M) av = *(const float4*)&A[(size_t)gr * K + k0 + a_kc];
            float4 bv = *(const float4*)&W[(size_t)(k0 + b_kr) * D_H + bn + b_col];
            __syncthreads();   // protect previous iteration's reads
            As[a_kc + 0][a_row] = av.x;
            As[a_kc + 1][a_row] = av.y;
            As[a_kc + 2][a_row] = av.z;
            As[a_kc + 3][a_row] = av.w;
            *(float4*)&Bs[b_kr][b_col] = bv;
            __syncthreads();
#pragma unroll
            for (int k = 0; k < BK; k++) {
                float4 a0 = *(const float4*)&As[k][ty * 8];
                float4 a1 = *(const float4*)&As[k][ty * 8 + 4];
                float4 b0 = *(const float4*)&Bs[k][tx * 8];
                float4 b1 = *(const float4*)&Bs[k][tx * 8 + 4];
                float a[8] = {a0.x, a0.y, a0.z, a0.w, a1.x, a1.y, a1.z, a1.w};
                float b[8] = {b0.x, b0.y, b0.z, b0.w, b1.x, b1.y, b1.z, b1.w};
#pragma unroll
                for (int i = 0; i < 8; i++)
#pragma unroll
                    for (int j = 0; j < 8; j++)
                        acc[i][j] = fmaf(a[i], b[j], acc[i][j]);
            }
        }
    }

    const int gn = bn + tx * 8;
    float bb[8];
#pragma unroll
    for (int j = 0; j < 8; j++) bb[j] = bias[gn + j];
#pragma unroll
    for (int i = 0; i < 8; i++) {
        int gm = bm + ty * 8 + i;
        if (gm >= M) continue;
        float4 o0, o1;
        o0.x = acc[i][0] + bb[0]; o0.y = acc[i][1] + bb[1];
        o0.z = acc[i][2] + bb[2]; o0.w = acc[i][3] + bb[3];
        o1.x = acc[i][4] + bb[4]; o1.y = acc[i][5] + bb[5];
        o1.z = acc[i][6] + bb[6]; o1.w = acc[i][7] + bb[7];
        if (do_relu) {
            o0.x = fmaxf(o0.x, 0.f); o0.y = fmaxf(o0.y, 0.f);
            o0.z = fmaxf(o0.z, 0.f); o0.w = fmaxf(o0.w, 0.f);
            o1.x = fmaxf(o1.x, 0.f); o1.y = fmaxf(o1.y, 0.f);
            o1.z = fmaxf(o1.z, 0.f); o1.w = fmaxf(o1.w, 0.f);
        }
        float* op = out + (size_t)gm * D_H + gn;
        *(float4*)op = o0;
        *(float4*)(op + 4) = o1;
    }
}

// ---------------- epilogue: copy raw out + log_softmax ------------------------
__global__ void emit_kernel(const float* __restrict__ in,
                            float* __restrict__ out_raw,
                            float* __restrict__ out_ls) {
    int row = blockIdx.x;
    int t = threadIdx.x;
    float v = in[row * D_H + t];
    __shared__ float red[D_H];
    red[t] = v;
    __syncthreads();
#pragma unroll
    for (int s = 128; s > 0; s >>= 1) {
        if (t < s) red[t] = fmaxf(red[t], red[t + s]);
        __syncthreads();
    }
    float m = red[0];
    __syncthreads();
    float e = expf(v - m);
    red[t] = e;
    __syncthreads();
#pragma unroll
    for (int s = 128; s > 0; s >>= 1) {
        if (t < s) red[t] += red[t + s];
        __syncthreads();
    }
    float ls = v - m - logf(red[0]);
    if (out_raw) out_raw[row * D_H + t] = v;
    out_ls[row * D_H + t] = ls;
}

// ---------------- launch ------------------------------------------------------
extern "C" void kernel_launch(void* const* d_in, const int* in_sizes, int n_in,
                              void* d_out, int out_size) {
    const float* x     = (const float*)d_in[0];
    const int* ei0     = (const int*)d_in[1];
    const int* ei1     = (const int*)d_in[2];
    const float* W_l0  = (const float*)d_in[3];
    const float* b_l0  = (const float*)d_in[4];
    const float* W_r0  = (const float*)d_in[5];
    const float* W_l1  = (const float*)d_in[6];
    const float* b_l1  = (const float*)d_in[7];
    const float* W_r1  = (const float*)d_in[8];
    float* out         = (float*)d_out;

    float *p_mean0, *p_h, *p_mean1, *p_out;
    int *p_cnt0, *p_rp0, *p_cur0, *p_col0;
    int *p_cnt1, *p_rp1, *p_cur1, *p_col1;
    cudaGetSymbolAddress((void**)&p_mean0, g_mean0);
    cudaGetSymbolAddress((void**)&p_h,     g_h);
    cudaGetSymbolAddress((void**)&p_mean1, g_mean1);
    cudaGetSymbolAddress((void**)&p_out,   g_out);
    cudaGetSymbolAddress((void**)&p_cnt0,  g_cnt0);
    cudaGetSymbolAddress((void**)&p_rp0,   g_rowptr0);
    cudaGetSymbolAddress((void**)&p_cur0,  g_cursor0);
    cudaGetSymbolAddress((void**)&p_col0,  g_col0);
    cudaGetSymbolAddress((void**)&p_cnt1,  g_cnt1);
    cudaGetSymbolAddress((void**)&p_rp1,   g_rowptr1);
    cudaGetSymbolAddress((void**)&p_cur1,  g_cursor1);
    cudaGetSymbolAddress((void**)&p_col1,  g_col1);

    zero_cnt_kernel<<<(N_DST0 + 255) / 256, 256>>>();

    // CSR build, layer 0
    count_kernel<<<(NEDGE0 + 255) / 256, 256>>>(ei0, p_cnt0, NEDGE0);
    scan_kernel<<<1, 1024>>>(p_cnt0, p_rp0, p_cur0, N_DST0);
    fill_kernel<<<(NEDGE0 + 255) / 256, 256>>>(ei0, p_cur0, p_col0, NEDGE0);
    // CSR build, layer 1 (independent of layer-0 compute)
    count_kernel<<<(NEDGE1 + 255) / 256, 256>>>(ei1, p_cnt1, NEDGE1);
    scan_kernel<<<1, 1024>>>(p_cnt1, p_rp1, p_cur1, N_DST1);
    fill_kernel<<<(NEDGE1 + 255) / 256, 256>>>(ei1, p_cur1, p_col1, NEDGE1);

    // layer 0 aggregate + GEMM: h = relu(mean0 @ W_l0 + b_l0 + x[:20000] @ W_r0)
    agg0_kernel<<<(N_DST0 * 32 + 255) / 256, 256>>>(x);
    gemm_dual_kernel<<<dim3(D_H / BN, (N_DST0 + BM - 1) / BM), 256>>>(
        p_mean0, x, W_l0, W_r0, b_l0, p_h, N_DST0, D_IN, 1);

    // layer 1 aggregate + GEMM: out = mean1 @ W_l1 + b_l1 + h[:4000] @ W_r1
    agg1_kernel<<<(N_DST1 * 32 + 255) / 256, 256>>>();
    gemm_dual_kernel<<<dim3(D_H / BN, (N_DST1 + BM - 1) / BM), 256>>>(
        p_mean1, p_h, W_l1, W_r1, b_l1, p_out, N_DST1, D_H, 0);

    // emit: reference returns (out, log_softmax(out)) -> concatenated if room
    const int NM = N_DST1 * D_H;
    float* out_raw = (out_size >= 2 * NM) ? out : nullptr;
    float* out_ls  = (out_size >= 2 * NM) ? out + NM : out;
    emit_kernel<<<N_DST1, D_H>>>(p_out, out_raw, out_ls);
}

// round 7
// speedup vs baseline: 1.0976x; 1.0976x over previous
#include <cuda_runtime.h>
#include <cstdint>

// ---------------- problem constants (fixed by reference setup) ----------------
#define N_SRC0 100000
#define N_DST0 20000
#define N_DST1 4000
#define NEDGE0 500000
#define NEDGE1 100000
#define D_IN 128
#define D_H 256

// ---------------- scratch (device globals; no allocation allowed) -------------
__device__ float g_mean0[N_DST0 * D_IN];  // layer0 segment means
__device__ float g_h[N_DST0 * D_H];       // layer0 output (relu'd)
__device__ float g_mean1[N_DST1 * D_H];   // layer1 segment means
__device__ float g_out[N_DST1 * D_H];     // layer1 raw output (pre-softmax)

__device__ int g_cnt0[N_DST0];            // per-dst edge counts (layer0)
__device__ int g_rowptr0[N_DST0 + 1];
__device__ int g_cursor0[N_DST0];
__device__ int g_col0[NEDGE0];            // CSR column (src) ids
__device__ int g_cnt1[N_DST1];
__device__ int g_rowptr1[N_DST1 + 1];
__device__ int g_cursor1[N_DST1];
__device__ int g_col1[NEDGE1];

// ---------------- zero counts ----------------
__global__ void zero_cnt_kernel() {
    int i = blockIdx.x * blockDim.x + threadIdx.x;
    if (i < N_DST0) g_cnt0[i] = 0;
    if (i < N_DST1) g_cnt1[i] = 0;
}

// ---------------- CSR build: fused count (both layers) ------------------------
__global__ void count2_kernel(const int* __restrict__ ei0,
                              const int* __restrict__ ei1) {
    int t = blockIdx.x * blockDim.x + threadIdx.x;
    if (t < NEDGE0) {
        atomicAdd(&g_cnt0[ei0[NEDGE0 + t]], 1);
    } else if (t < NEDGE0 + NEDGE1) {
        int e = t - NEDGE0;
        atomicAdd(&g_cnt1[ei1[NEDGE1 + e]], 1);
    }
}

// ---------------- warp-shuffle scan, both layers in one launch ----------------
// block 0 scans layer0 counts, block 1 scans layer1 counts.
__global__ void __launch_bounds__(1024, 1)
scan2_kernel() {
    const int layer = blockIdx.x;
    const int n     = layer ? N_DST1 : N_DST0;
    int* __restrict__ cnt    = layer ? g_cnt1    : g_cnt0;
    int* __restrict__ rowptr = layer ? g_rowptr1 : g_rowptr0;
    int* __restrict__ cursor = layer ? g_cursor1 : g_cursor0;

    __shared__ int wsum[32];
    __shared__ int carry_s;
    const int tid  = threadIdx.x;
    const int lane = tid & 31;
    const int wid  = tid >> 5;
    if (tid == 0) carry_s = 0;
    __syncthreads();

    for (int base = 0; base < n; base += 1024) {
        int i = base + tid;
        int v = (i < n) ? cnt[i] : 0;
        // warp inclusive scan via shfl
        int s = v;
#pragma unroll
        for (int off = 1; off < 32; off <<= 1) {
            int t = __shfl_up_sync(0xffffffffu, s, off);
            if (lane >= off) s += t;
        }
        if (lane == 31) wsum[wid] = s;
        __syncthreads();
        if (wid == 0) {
            int ws = wsum[lane];
#pragma unroll
            for (int off = 1; off < 32; off <<= 1) {
                int t = __shfl_up_sync(0xffffffffu, ws, off);
                if (lane >= off) ws += t;
            }
            wsum[lane] = ws;
        }
        __syncthreads();
        int blockoff = (wid > 0) ? wsum[wid - 1] : 0;
        int excl = carry_s + blockoff + s - v;   // exclusive prefix
        if (i < n) { rowptr[i] = excl; cursor[i] = excl; }
        __syncthreads();                          // all reads of carry_s done
        if (tid == 0) carry_s += wsum[31];
        __syncthreads();
    }
    if (tid == 0) rowptr[n] = carry_s;
}

// ---------------- CSR build: fused fill (both layers) -------------------------
__global__ void fill2_kernel(const int* __restrict__ ei0,
                             const int* __restrict__ ei1) {
    int t = blockIdx.x * blockDim.x + threadIdx.x;
    if (t < NEDGE0) {
        int d = ei0[NEDGE0 + t];
        int slot = atomicAdd(&g_cursor0[d], 1);
        g_col0[slot] = ei0[t];
    } else if (t < NEDGE0 + NEDGE1) {
        int e = t - NEDGE0;
        int d = ei1[NEDGE1 + e];
        int slot = atomicAdd(&g_cursor1[d], 1);
        g_col1[slot] = ei1[e];
    }
}

// ---------------- dst-major aggregation (mean), no float atomics --------------
// layer0: D=128, one warp per dst, lane holds one float4; unroll 4 for MLP.
__global__ void agg0_kernel(const float* __restrict__ x) {
    int w = (blockIdx.x * blockDim.x + threadIdx.x) >> 5;
    int lane = threadIdx.x & 31;
    if (w >= N_DST0) return;
    int beg = g_rowptr0[w], end = g_rowptr0[w + 1];
    float4 a0 = make_float4(0.f, 0.f, 0.f, 0.f);
    float4 a1 = a0, a2 = a0, a3 = a0;
    int e = beg;
    for (; e + 4 <= end; e += 4) {
        int s0 = g_col0[e], s1 = g_col0[e + 1], s2 = g_col0[e + 2], s3 = g_col0[e + 3];
        float4 v0 = ((const float4*)(x + (size_t)s0 * D_IN))[lane];
        float4 v1 = ((const float4*)(x + (size_t)s1 * D_IN))[lane];
        float4 v2 = ((const float4*)(x + (size_t)s2 * D_IN))[lane];
        float4 v3 = ((const float4*)(x + (size_t)s3 * D_IN))[lane];
        a0.x += v0.x; a0.y += v0.y; a0.z += v0.z; a0.w += v0.w;
        a1.x += v1.x; a1.y += v1.y; a1.z += v1.z; a1.w += v1.w;
        a2.x += v2.x; a2.y += v2.y; a2.z += v2.z; a2.w += v2.w;
        a3.x += v3.x; a3.y += v3.y; a3.z += v3.z; a3.w += v3.w;
    }
    for (; e < end; e++) {
        float4 v = ((const float4*)(x + (size_t)g_col0[e] * D_IN))[lane];
        a0.x += v.x; a0.y += v.y; a0.z += v.z; a0.w += v.w;
    }
    a0.x += a1.x + a2.x + a3.x;
    a0.y += a1.y + a2.y + a3.y;
    a0.z += a1.z + a2.z + a3.z;
    a0.w += a1.w + a2.w + a3.w;
    float s = 1.f / fmaxf((float)(end - beg), 1.f);
    a0.x *= s; a0.y *= s; a0.z *= s; a0.w *= s;
    ((float4*)(g_mean0 + (size_t)w * D_IN))[lane] = a0;
}

// layer1: D=256, one warp per dst, lane holds two float4s; unroll 2 -> MLP 4.
__global__ void agg1_kernel() {
    int w = (blockIdx.x * blockDim.x + threadIdx.x) >> 5;
    int lane = threadIdx.x & 31;
    if (w >= N_DST1) return;
    int beg = g_rowptr1[w], end = g_rowptr1[w + 1];
    float4 a0 = make_float4(0.f, 0.f, 0.f, 0.f);
    float4 a1 = a0, b0 = a0, b1 = a0;
    int e = beg;
    for (; e + 2 <= end; e += 2) {
        const float4* h0 = (const float4*)(g_h + (size_t)g_col1[e] * D_H);
        const float4* h1 = (const float4*)(g_h + (size_t)g_col1[e + 1] * D_H);
        float4 u0 = h0[lane], u1 = h0[lane + 32];
        float4 w0 = h1[lane], w1 = h1[lane + 32];
        a0.x += u0.x; a0.y += u0.y; a0.z += u0.z; a0.w += u0.w;
        a1.x += u1.x; a1.y += u1.y; a1.z += u1.z; a1.w += u1.w;
        b0.x += w0.x; b0.y += w0.y; b0.z += w0.z; b0.w += w0.w;
        b1.x += w1.x; b1.y += w1.y; b1.z += w1.z; b1.w += w1.w;
    }
    if (e < end) {
        const float4* h0 = (const float4*)(g_h + (size_t)g_col1[e] * D_H);
        float4 u0 = h0[lane], u1 = h0[lane + 32];
        a0.x += u0.x; a0.y += u0.y; a0.z += u0.z; a0.w += u0.w;
        a1.x += u1.x; a1.y += u1.y; a1.z += u1.z; a1.w += u1.w;
    }
    a0.x += b0.x; a0.y += b0.y; a0.z += b0.z; a0.w += b0.w;
    a1.x += b1.x; a1.y += b1.y; a1.z += b1.z; a1.w += b1.w;
    float s = 1.f / fmaxf((float)(end - beg), 1.f);
    a0.x *= s; a0.y *= s; a0.z *= s; a0.w *= s;
    a1.x *= s; a1.y *= s; a1.z *= s; a1.w *= s;
    float4* op = (float4*)(g_mean1 + (size_t)w * D_H);
    op[lane] = a0;
    op[lane + 32] = a1;
}

// ---------------- dual-A GEMM: out = A1@W1 + A2@W2 + b  (opt relu) ------------
// 128x128x8 tile, 256 threads, 8x8 microtile, As transposed for float4 LDS.
#define BM 128
#define BN 128
#define BK 8
__global__ void __launch_bounds__(256, 2)
gemm_dual_kernel(const float* __restrict__ A1,
                 const float* __restrict__ A2,
                 const float* __restrict__ W1, const float* __restrict__ W2,
                 const float* __restrict__ bias,
                 float* __restrict__ out, int M, int K, int do_relu) {
    __shared__ float As[BK][BM];     // transposed A tile
    __shared__ float Bs[BK][BN];

    const int tid = threadIdx.x;
    const int tx = tid & 15;         // 0..15 -> 8 cols each
    const int ty = tid >> 4;         // 0..15 -> 8 rows each
    const int bm = blockIdx.y * BM;
    const int bn = blockIdx.x * BN;

    const int a_row = tid >> 1;            // 0..127
    const int a_kc  = (tid & 1) * 4;       // 0 or 4
    const int b_kr  = tid >> 5;            // 0..7
    const int b_col = (tid & 31) * 4;      // 0..124

    float acc[8][8];
#pragma unroll
    for (int i = 0; i < 8; i++)
#pragma unroll
        for (int j = 0; j < 8; j++) acc[i][j] = 0.f;

    for (int pass = 0; pass < 2; pass++) {
        const float* __restrict__ A = pass ? A2 : A1;
        const float* __restrict__ W = pass ? W2 : W1;
        const int gr = bm + a_row;

        for (int k0 = 0; k0 < K; k0 += BK) {
            float4 av = make_float4(0.f, 0.f, 0.f, 0.f);
            if (gr < M) av = *(const float4*)&A[(size_t)gr * K + k0 + a_kc];
            float4 bv = *(const float4*)&W[(size_t)(k0 + b_kr) * D_H + bn + b_col];
            __syncthreads();   // protect previous iteration's reads
            As[a_kc + 0][a_row] = av.x;
            As[a_kc + 1][a_row] = av.y;
            As[a_kc + 2][a_row] = av.z;
            As[a_kc + 3][a_row] = av.w;
            *(float4*)&Bs[b_kr][b_col] = bv;
            __syncthreads();
#pragma unroll
            for (int k = 0; k < BK; k++) {
                float4 a0 = *(const float4*)&As[k][ty * 8];
                float4 a1 = *(const float4*)&As[k][ty * 8 + 4];
                float4 b0 = *(const float4*)&Bs[k][tx * 8];
                float4 b1 = *(const float4*)&Bs[k][tx * 8 + 4];
                float a[8] = {a0.x, a0.y, a0.z, a0.w, a1.x, a1.y, a1.z, a1.w};
                float b[8] = {b0.x, b0.y, b0.z, b0.w, b1.x, b1.y, b1.z, b1.w};
#pragma unroll
                for (int i = 0; i < 8; i++)
#pragma unroll
                    for (int j = 0; j < 8; j++)
                        acc[i][j] = fmaf(a[i], b[j], acc[i][j]);
            }
        }
    }

    const int gn = bn + tx * 8;
    float bb[8];
#pragma unroll
    for (int j = 0; j < 8; j++) bb[j] = bias[gn + j];
#pragma unroll
    for (int i = 0; i < 8; i++) {
        int gm = bm + ty * 8 + i;
        if (gm >= M) continue;
        float4 o0, o1;
        o0.x = acc[i][0] + bb[0]; o0.y = acc[i][1] + bb[1];
        o0.z = acc[i][2] + bb[2]; o0.w = acc[i][3] + bb[3];
        o1.x = acc[i][4] + bb[4]; o1.y = acc[i][5] + bb[5];
        o1.z = acc[i][6] + bb[6]; o1.w = acc[i][7] + bb[7];
        if (do_relu) {
            o0.x = fmaxf(o0.x, 0.f); o0.y = fmaxf(o0.y, 0.f);
            o0.z = fmaxf(o0.z, 0.f); o0.w = fmaxf(o0.w, 0.f);
            o1.x = fmaxf(o1.x, 0.f); o1.y = fmaxf(o1.y, 0.f);
            o1.z = fmaxf(o1.z, 0.f); o1.w = fmaxf(o1.w, 0.f);
        }
        float* op = out + (size_t)gm * D_H + gn;
        *(float4*)op = o0;
        *(float4*)(op + 4) = o1;
    }
}

// ---------------- epilogue: copy raw out + log_softmax ------------------------
__global__ void emit_kernel(const float* __restrict__ in,
                            float* __restrict__ out_raw,
                            float* __restrict__ out_ls) {
    int row = blockIdx.x;
    int t = threadIdx.x;
    float v = in[row * D_H + t];
    __shared__ float red[D_H];
    red[t] = v;
    __syncthreads();
#pragma unroll
    for (int s = 128; s > 0; s >>= 1) {
        if (t < s) red[t] = fmaxf(red[t], red[t + s]);
        __syncthreads();
    }
    float m = red[0];
    __syncthreads();
    float e = expf(v - m);
    red[t] = e;
    __syncthreads();
#pragma unroll
    for (int s = 128; s > 0; s >>= 1) {
        if (t < s) red[t] += red[t + s];
        __syncthreads();
    }
    float ls = v - m - logf(red[0]);
    if (out_raw) out_raw[row * D_H + t] = v;
    out_ls[row * D_H + t] = ls;
}

// ---------------- launch ------------------------------------------------------
extern "C" void kernel_launch(void* const* d_in, const int* in_sizes, int n_in,
                              void* d_out, int out_size) {
    const float* x     = (const float*)d_in[0];
    const int* ei0     = (const int*)d_in[1];
    const int* ei1     = (const int*)d_in[2];
    const float* W_l0  = (const float*)d_in[3];
    const float* b_l0  = (const float*)d_in[4];
    const float* W_r0  = (const float*)d_in[5];
    const float* W_l1  = (const float*)d_in[6];
    const float* b_l1  = (const float*)d_in[7];
    const float* W_r1  = (const float*)d_in[8];
    float* out         = (float*)d_out;

    float *p_mean0, *p_h, *p_mean1, *p_out;
    cudaGetSymbolAddress((void**)&p_mean0, g_mean0);
    cudaGetSymbolAddress((void**)&p_h,     g_h);
    cudaGetSymbolAddress((void**)&p_mean1, g_mean1);
    cudaGetSymbolAddress((void**)&p_out,   g_out);

    // CSR build (both layers fused per stage)
    zero_cnt_kernel<<<(N_DST0 + 255) / 256, 256>>>();
    count2_kernel<<<(NEDGE0 + NEDGE1 + 255) / 256, 256>>>(ei0, ei1);
    scan2_kernel<<<2, 1024>>>();
    fill2_kernel<<<(NEDGE0 + NEDGE1 + 255) / 256, 256>>>(ei0, ei1);

    // layer 0 aggregate + GEMM: h = relu(mean0 @ W_l0 + b_l0 + x[:20000] @ W_r0)
    agg0_kernel<<<(N_DST0 * 32 + 255) / 256, 256>>>(x);
    gemm_dual_kernel<<<dim3(D_H / BN, (N_DST0 + BM - 1) / BM), 256>>>(
        p_mean0, x, W_l0, W_r0, b_l0, p_h, N_DST0, D_IN, 1);

    // layer 1 aggregate + GEMM: out = mean1 @ W_l1 + b_l1 + h[:4000] @ W_r1
    agg1_kernel<<<(N_DST1 * 32 + 255) / 256, 256>>>();
    gemm_dual_kernel<<<dim3(D_H / BN, (N_DST1 + BM - 1) / BM), 256>>>(
        p_mean1, p_h, W_l1, W_r1, b_l1, p_out, N_DST1, D_H, 0);

    // emit: reference returns (out, log_softmax(out)) -> concatenated if room
    const int NM = N_DST1 * D_H;
    float* out_raw = (out_size >= 2 * NM) ? out : nullptr;
    float* out_ls  = (out_size >= 2 * NM) ? out + NM : out;
    emit_kernel<<<N_DST1, D_H>>>(p_out, out_raw, out_ls);
}

// round 9
// speedup vs baseline: 1.9848x; 1.8083x over previous
#include <cuda_runtime.h>
#include <cstdint>

// ---------------- problem constants (fixed by reference setup) ----------------
#define N_SRC0 100000
#define N_DST0 20000
#define N_DST1 4000
#define NEDGE0 500000
#define NEDGE1 100000
#define D_IN 128
#define D_H 256

// ---------------- scratch (device globals; no allocation allowed) -------------
__device__ float g_mean0[N_DST0 * D_IN];  // layer0 segment means
__device__ float g_h[N_DST0 * D_H];       // layer0 output (relu'd)
__device__ float g_mean1[N_DST1 * D_H];   // layer1 segment means
__device__ float g_out[N_DST1 * D_H];     // layer1 raw output (pre-softmax)

__device__ int g_cnt0[N_DST0];
__device__ int g_rowptr0[N_DST0 + 1];
__device__ int g_cursor0[N_DST0];
__device__ int g_col0[NEDGE0];
__device__ int g_cnt1[N_DST1];
__device__ int g_rowptr1[N_DST1 + 1];
__device__ int g_cursor1[N_DST1];
__device__ int g_col1[NEDGE1];

// ---------------- zero counts ----------------
__global__ void zero_cnt_kernel() {
    int i = blockIdx.x * blockDim.x + threadIdx.x;
    if (i < N_DST0) g_cnt0[i] = 0;
    if (i < N_DST1) g_cnt1[i] = 0;
}

// ---------------- CSR build: fused count (both layers) ------------------------
__global__ void count2_kernel(const int* __restrict__ ei0,
                              const int* __restrict__ ei1) {
    int t = blockIdx.x * blockDim.x + threadIdx.x;
    if (t < NEDGE0) {
        atomicAdd(&g_cnt0[ei0[NEDGE0 + t]], 1);
    } else if (t < NEDGE0 + NEDGE1) {
        int e = t - NEDGE0;
        atomicAdd(&g_cnt1[ei1[NEDGE1 + e]], 1);
    }
}

// ---------------- warp-shuffle scan, both layers in one launch ----------------
__global__ void __launch_bounds__(1024, 1)
scan2_kernel() {
    const int layer = blockIdx.x;
    const int n     = layer ? N_DST1 : N_DST0;
    int* __restrict__ cnt    = layer ? g_cnt1    : g_cnt0;
    int* __restrict__ rowptr = layer ? g_rowptr1 : g_rowptr0;
    int* __restrict__ cursor = layer ? g_cursor1 : g_cursor0;

    __shared__ int wsum[32];
    __shared__ int carry_s;
    const int tid  = threadIdx.x;
    const int lane = tid & 31;
    const int wid  = tid >> 5;
    if (tid == 0) carry_s = 0;
    __syncthreads();

    for (int base = 0; base < n; base += 1024) {
        int i = base + tid;
        int v = (i < n) ? cnt[i] : 0;
        int s = v;
#pragma unroll
        for (int off = 1; off < 32; off <<= 1) {
            int t = __shfl_up_sync(0xffffffffu, s, off);
            if (lane >= off) s += t;
        }
        if (lane == 31) wsum[wid] = s;
        __syncthreads();
        if (wid == 0) {
            int ws = wsum[lane];
#pragma unroll
            for (int off = 1; off < 32; off <<= 1) {
                int t = __shfl_up_sync(0xffffffffu, ws, off);
                if (lane >= off) ws += t;
            }
            wsum[lane] = ws;
        }
        __syncthreads();
        int blockoff = (wid > 0) ? wsum[wid - 1] : 0;
        int excl = carry_s + blockoff + s - v;
        if (i < n) { rowptr[i] = excl; cursor[i] = excl; }
        __syncthreads();
        if (tid == 0) carry_s += wsum[31];
        __syncthreads();
    }
    if (tid == 0) rowptr[n] = carry_s;
}

// ---------------- CSR build: fused fill (both layers) -------------------------
__global__ void fill2_kernel(const int* __restrict__ ei0,
                             const int* __restrict__ ei1) {
    int t = blockIdx.x * blockDim.x + threadIdx.x;
    if (t < NEDGE0) {
        int d = ei0[NEDGE0 + t];
        int slot = atomicAdd(&g_cursor0[d], 1);
        g_col0[slot] = ei0[t];
    } else if (t < NEDGE0 + NEDGE1) {
        int e = t - NEDGE0;
        int d = ei1[NEDGE1 + e];
        int slot = atomicAdd(&g_cursor1[d], 1);
        g_col1[slot] = ei1[e];
    }
}

// ---------------- dst-major aggregation (mean), no float atomics --------------
__global__ void agg0_kernel(const float* __restrict__ x) {
    int w = (blockIdx.x * blockDim.x + threadIdx.x) >> 5;
    int lane = threadIdx.x & 31;
    if (w >= N_DST0) return;
    int beg = g_rowptr0[w], end = g_rowptr0[w + 1];
    float4 a0 = make_float4(0.f, 0.f, 0.f, 0.f);
    float4 a1 = a0, a2 = a0, a3 = a0;
    int e = beg;
    for (; e + 4 <= end; e += 4) {
        int s0 = g_col0[e], s1 = g_col0[e + 1], s2 = g_col0[e + 2], s3 = g_col0[e + 3];
        float4 v0 = ((const float4*)(x + (size_t)s0 * D_IN))[lane];
        float4 v1 = ((const float4*)(x + (size_t)s1 * D_IN))[lane];
        float4 v2 = ((const float4*)(x + (size_t)s2 * D_IN))[lane];
        float4 v3 = ((const float4*)(x + (size_t)s3 * D_IN))[lane];
        a0.x += v0.x; a0.y += v0.y; a0.z += v0.z; a0.w += v0.w;
        a1.x += v1.x; a1.y += v1.y; a1.z += v1.z; a1.w += v1.w;
        a2.x += v2.x; a2.y += v2.y; a2.z += v2.z; a2.w += v2.w;
        a3.x += v3.x; a3.y += v3.y; a3.z += v3.z; a3.w += v3.w;
    }
    for (; e < end; e++) {
        float4 v = ((const float4*)(x + (size_t)g_col0[e] * D_IN))[lane];
        a0.x += v.x; a0.y += v.y; a0.z += v.z; a0.w += v.w;
    }
    a0.x += a1.x + a2.x + a3.x;
    a0.y += a1.y + a2.y + a3.y;
    a0.z += a1.z + a2.z + a3.z;
    a0.w += a1.w + a2.w + a3.w;
    float s = 1.f / fmaxf((float)(end - beg), 1.f);
    a0.x *= s; a0.y *= s; a0.z *= s; a0.w *= s;
    ((float4*)(g_mean0 + (size_t)w * D_IN))[lane] = a0;
}

__global__ void agg1_kernel() {
    int w = (blockIdx.x * blockDim.x + threadIdx.x) >> 5;
    int lane = threadIdx.x & 31;
    if (w >= N_DST1) return;
    int beg = g_rowptr1[w], end = g_rowptr1[w + 1];
    float4 a0 = make_float4(0.f, 0.f, 0.f, 0.f);
    float4 a1 = a0, b0 = a0, b1 = a0;
    int e = beg;
    for (; e + 2 <= end; e += 2) {
        const float4* h0 = (const float4*)(g_h + (size_t)g_col1[e] * D_H);
        const float4* h1 = (const float4*)(g_h + (size_t)g_col1[e + 1] * D_H);
        float4 u0 = h0[lane], u1 = h0[lane + 32];
        float4 w0 = h1[lane], w1 = h1[lane + 32];
        a0.x += u0.x; a0.y += u0.y; a0.z += u0.z; a0.w += u0.w;
        a1.x += u1.x; a1.y += u1.y; a1.z += u1.z; a1.w += u1.w;
        b0.x += w0.x; b0.y += w0.y; b0.z += w0.z; b0.w += w0.w;
        b1.x += w1.x; b1.y += w1.y; b1.z += w1.z; b1.w += w1.w;
    }
    if (e < end) {
        const float4* h0 = (const float4*)(g_h + (size_t)g_col1[e] * D_H);
        float4 u0 = h0[lane], u1 = h0[lane + 32];
        a0.x += u0.x; a0.y += u0.y; a0.z += u0.z; a0.w += u0.w;
        a1.x += u1.x; a1.y += u1.y; a1.z += u1.z; a1.w += u1.w;
    }
    a0.x += b0.x; a0.y += b0.y; a0.z += b0.z; a0.w += b0.w;
    a1.x += b1.x; a1.y += b1.y; a1.z += b1.z; a1.w += b1.w;
    float s = 1.f / fmaxf((float)(end - beg), 1.f);
    a0.x *= s; a0.y *= s; a0.z *= s; a0.w *= s;
    a1.x *= s; a1.y *= s; a1.z *= s; a1.w *= s;
    float4* op = (float4*)(g_mean1 + (size_t)w * D_H);
    op[lane] = a0;
    op[lane + 32] = a1;
}

// ---------------- TF32 tensor-core dual-A GEMM --------------------------------
// out = A1@W1 + A2@W2 + b (opt relu). Block 128x128xBK16, 8 warps, warp 64x32.
// mma.sync.m16n8k8 tf32. Inputs converted to tf32 at smem-store time.
#define BM 128
#define BN 128
#define BK 16
#define AS_STRIDE 20    // conflict-free A fragment reads
#define BS_STRIDE 136   // conflict-free B fragment reads

__device__ __forceinline__ uint32_t f2tf32(float f) {
    uint32_t u;
    asm("cvt.rna.tf32.f32 %0, %1;" : "=r"(u) : "f"(f));
    return u;
}

__global__ void __launch_bounds__(256, 2)
gemm_dual_tf32_kernel(const float* __restrict__ A1,
                      const float* __restrict__ A2,
                      const float* __restrict__ W1, const float* __restrict__ W2,
                      const float* __restrict__ bias,
                      float* __restrict__ out, int M, int K, int do_relu) {
    __shared__ uint32_t As[BM * AS_STRIDE];   // [m][k] tf32 bits
    __shared__ uint32_t Bs[BK * BS_STRIDE];   // [k][n] tf32 bits

    const int tid  = threadIdx.x;
    const int lane = tid & 31;
    const int wrp  = tid >> 5;               // 0..7
    const int m_warp = (wrp & 1) * 64;       // 2 row blocks of 64
    const int n_warp = (wrp >> 1) * 32;      // 4 col blocks of 32
    const int bm = blockIdx.y * BM;
    const int bn = blockIdx.x * BN;

    // global->smem mapping
    const int a_r  = tid >> 2;               // 0..63 (and +64)
    const int a_kc = (tid & 3) * 4;          // 0,4,8,12
    const int b_kr = tid >> 5;               // 0..7 (and +8)
    const int b_c  = (tid & 31) * 4;

    float acc[4][4][4];                      // [mt][nt][reg]
#pragma unroll
    for (int i = 0; i < 4; i++)
#pragma unroll
        for (int j = 0; j < 4; j++)
#pragma unroll
            for (int r = 0; r < 4; r++) acc[i][j][r] = 0.f;

    const int fr = lane >> 2;                // 0..7
    const int fc = lane & 3;                 // 0..3

    for (int pass = 0; pass < 2; pass++) {
        const float* __restrict__ A = pass ? A2 : A1;
        const float* __restrict__ W = pass ? W2 : W1;
        const int gr0 = bm + a_r;
        const int gr1 = gr0 + 64;

        for (int k0 = 0; k0 < K; k0 += BK) {
            float4 av0 = make_float4(0.f, 0.f, 0.f, 0.f);
            float4 av1 = av0;
            if (gr0 < M) av0 = *(const float4*)&A[(size_t)gr0 * K + k0 + a_kc];
            if (gr1 < M) av1 = *(const float4*)&A[(size_t)gr1 * K + k0 + a_kc];
            float4 bv0 = *(const float4*)&W[(size_t)(k0 + b_kr) * D_H + bn + b_c];
            float4 bv1 = *(const float4*)&W[(size_t)(k0 + b_kr + 8) * D_H + bn + b_c];
            __syncthreads();  // protect previous iteration's reads
            {
                uint32_t* p0 = &As[a_r * AS_STRIDE + a_kc];
                p0[0] = f2tf32(av0.x); p0[1] = f2tf32(av0.y);
                p0[2] = f2tf32(av0.z); p0[3] = f2tf32(av0.w);
                uint32_t* p1 = &As[(a_r + 64) * AS_STRIDE + a_kc];
                p1[0] = f2tf32(av1.x); p1[1] = f2tf32(av1.y);
                p1[2] = f2tf32(av1.z); p1[3] = f2tf32(av1.w);
                uint32_t* q0 = &Bs[b_kr * BS_STRIDE + b_c];
                q0[0] = f2tf32(bv0.x); q0[1] = f2tf32(bv0.y);
                q0[2] = f2tf32(bv0.z); q0[3] = f2tf32(bv0.w);
                uint32_t* q1 = &Bs[(b_kr + 8) * BS_STRIDE + b_c];
                q1[0] = f2tf32(bv1.x); q1[1] = f2tf32(bv1.y);
                q1[2] = f2tf32(bv1.z); q1[3] = f2tf32(bv1.w);
            }
            __syncthreads();

#pragma unroll
            for (int ks = 0; ks < BK; ks += 8) {
                uint32_t af[4][4];
#pragma unroll
                for (int mt = 0; mt < 4; mt++) {
                    int rb = m_warp + mt * 16 + fr;
                    af[mt][0] = As[rb * AS_STRIDE + ks + fc];
                    af[mt][1] = As[(rb + 8) * AS_STRIDE + ks + fc];
                    af[mt][2] = As[rb * AS_STRIDE + ks + fc + 4];
                    af[mt][3] = As[(rb + 8) * AS_STRIDE + ks + fc + 4];
                }
                uint32_t bf[4][2];
#pragma unroll
                for (int nt = 0; nt < 4; nt++) {
                    int nb = n_warp + nt * 8 + fr;
                    bf[nt][0] = Bs[(ks + fc) * BS_STRIDE + nb];
                    bf[nt][1] = Bs[(ks + fc + 4) * BS_STRIDE + nb];
                }
#pragma unroll
                for (int mt = 0; mt < 4; mt++)
#pragma unroll
                    for (int nt = 0; nt < 4; nt++) {
                        asm volatile(
                            "mma.sync.aligned.m16n8k8.row.col.f32.tf32.tf32.f32 "
                            "{%0,%1,%2,%3}, {%4,%5,%6,%7}, {%8,%9}, {%0,%1,%2,%3};"
                            : "+f"(acc[mt][nt][0]), "+f"(acc[mt][nt][1]),
                              "+f"(acc[mt][nt][2]), "+f"(acc[mt][nt][3])
                            : "r"(af[mt][0]), "r"(af[mt][1]),
                              "r"(af[mt][2]), "r"(af[mt][3]),
                              "r"(bf[nt][0]), "r"(bf[nt][1]));
                    }
            }
        }
    }

    // epilogue: c0,c1 at (fr, 2*fc+{0,1}), c2,c3 at (fr+8, same)
#pragma unroll
    for (int mt = 0; mt < 4; mt++) {
#pragma unroll
        for (int nt = 0; nt < 4; nt++) {
            int col = bn + n_warp + nt * 8 + fc * 2;
            float b0 = bias[col], b1 = bias[col + 1];
            int r0 = bm + m_warp + mt * 16 + fr;
            int r1 = r0 + 8;
            float v0 = acc[mt][nt][0] + b0, v1 = acc[mt][nt][1] + b1;
            float v2 = acc[mt][nt][2] + b0, v3 = acc[mt][nt][3] + b1;
            if (do_relu) {
                v0 = fmaxf(v0, 0.f); v1 = fmaxf(v1, 0.f);
                v2 = fmaxf(v2, 0.f); v3 = fmaxf(v3, 0.f);
            }
            if (r0 < M) *(float2*)&out[(size_t)r0 * D_H + col] = make_float2(v0, v1);
            if (r1 < M) *(float2*)&out[(size_t)r1 * D_H + col] = make_float2(v2, v3);
        }
    }
}

// ---------------- epilogue: copy raw out + log_softmax ------------------------
__global__ void emit_kernel(const float* __restrict__ in,
                            float* __restrict__ out_raw,
                            float* __restrict__ out_ls) {
    int row = blockIdx.x;
    int t = threadIdx.x;
    float v = in[row * D_H + t];
    __shared__ float red[D_H];
    red[t] = v;
    __syncthreads();
#pragma unroll
    for (int s = 128; s > 0; s >>= 1) {
        if (t < s) red[t] = fmaxf(red[t], red[t + s]);
        __syncthreads();
    }
    float m = red[0];
    __syncthreads();
    float e = expf(v - m);
    red[t] = e;
    __syncthreads();
#pragma unroll
    for (int s = 128; s > 0; s >>= 1) {
        if (t < s) red[t] += red[t + s];
        __syncthreads();
    }
    float ls = v - m - logf(red[0]);
    if (out_raw) out_raw[row * D_H + t] = v;
    out_ls[row * D_H + t] = ls;
}

// ---------------- launch ------------------------------------------------------
extern "C" void kernel_launch(void* const* d_in, const int* in_sizes, int n_in,
                              void* d_out, int out_size) {
    const float* x     = (const float*)d_in[0];
    const int* ei0     = (const int*)d_in[1];
    const int* ei1     = (const int*)d_in[2];
    const float* W_l0  = (const float*)d_in[3];
    const float* b_l0  = (const float*)d_in[4];
    const float* W_r0  = (const float*)d_in[5];
    const float* W_l1  = (const float*)d_in[6];
    const float* b_l1  = (const float*)d_in[7];
    const float* W_r1  = (const float*)d_in[8];
    float* out         = (float*)d_out;

    float *p_mean0, *p_h, *p_mean1, *p_out;
    cudaGetSymbolAddress((void**)&p_mean0, g_mean0);
    cudaGetSymbolAddress((void**)&p_h,     g_h);
    cudaGetSymbolAddress((void**)&p_mean1, g_mean1);
    cudaGetSymbolAddress((void**)&p_out,   g_out);

    // CSR build (both layers fused per stage)
    zero_cnt_kernel<<<(N_DST0 + 255) / 256, 256>>>();
    count2_kernel<<<(NEDGE0 + NEDGE1 + 255) / 256, 256>>>(ei0, ei1);
    scan2_kernel<<<2, 1024>>>();
    fill2_kernel<<<(NEDGE0 + NEDGE1 + 255) / 256, 256>>>(ei0, ei1);

    // layer 0: h = relu(mean0 @ W_l0 + b_l0 + x[:20000] @ W_r0)
    agg0_kernel<<<(N_DST0 * 32 + 255) / 256, 256>>>(x);
    gemm_dual_tf32_kernel<<<dim3(D_H / BN, (N_DST0 + BM - 1) / BM), 256>>>(
        p_mean0, x, W_l0, W_r0, b_l0, p_h, N_DST0, D_IN, 1);

    // layer 1: out = mean1 @ W_l1 + b_l1 + h[:4000] @ W_r1
    agg1_kernel<<<(N_DST1 * 32 + 255) / 256, 256>>>();
    gemm_dual_tf32_kernel<<<dim3(D_H / BN, (N_DST1 + BM - 1) / BM), 256>>>(
        p_mean1, p_h, W_l1, W_r1, b_l1, p_out, N_DST1, D_H, 0);

    // emit: reference returns (out, log_softmax(out)) -> concatenated if room
    const int NM = N_DST1 * D_H;
    float* out_raw = (out_size >= 2 * NM) ? out : nullptr;
    float* out_ls  = (out_size >= 2 * NM) ? out + NM : out;
    emit_kernel<<<N_DST1, D_H>>>(p_out, out_raw, out_ls);
}

// round 10
// speedup vs baseline: 2.0646x; 1.0402x over previous
#include <cuda_runtime.h>
#include <cstdint>

// ---------------- problem constants (fixed by reference setup) ----------------
#define N_SRC0 100000
#define N_DST0 20000
#define N_DST1 4000
#define NEDGE0 500000
#define NEDGE1 100000
#define D_IN 128
#define D_H 256

// ---------------- scratch (device globals; no allocation allowed) -------------
__device__ float g_mean0[N_DST0 * D_IN];  // layer0 segment means
__device__ float g_h[N_DST0 * D_H];       // layer0 output (relu'd)
__device__ float g_mean1[N_DST1 * D_H];   // layer1 segment means
__device__ float g_out[N_DST1 * D_H];     // layer1 raw output (pre-softmax)

__device__ int g_cnt0[N_DST0];
__device__ int g_rowptr0[N_DST0 + 1];
__device__ int g_cursor0[N_DST0];
__device__ int g_col0[NEDGE0];
__device__ int g_cnt1[N_DST1];
__device__ int g_rowptr1[N_DST1 + 1];
__device__ int g_cursor1[N_DST1];
__device__ int g_col1[NEDGE1];

// ---------------- CSR build: fused count (both layers), 4 edges/thread --------
__global__ void count2_kernel(const int* __restrict__ ei0,
                              const int* __restrict__ ei1) {
    const int Q0 = NEDGE0 / 4, Q1 = NEDGE1 / 4;
    int t = blockIdx.x * blockDim.x + threadIdx.x;
    if (t < Q0) {
        int4 d = ((const int4*)(ei0 + NEDGE0))[t];
        atomicAdd(&g_cnt0[d.x], 1);
        atomicAdd(&g_cnt0[d.y], 1);
        atomicAdd(&g_cnt0[d.z], 1);
        atomicAdd(&g_cnt0[d.w], 1);
    } else if (t < Q0 + Q1) {
        int4 d = ((const int4*)(ei1 + NEDGE1))[t - Q0];
        atomicAdd(&g_cnt1[d.x], 1);
        atomicAdd(&g_cnt1[d.y], 1);
        atomicAdd(&g_cnt1[d.z], 1);
        atomicAdd(&g_cnt1[d.w], 1);
    }
}

// ---------------- scan: 8 elements/thread, warp-shuffle, 2 blocks -------------
__global__ void __launch_bounds__(1024, 1)
scan2_kernel() {
    const int layer = blockIdx.x;
    const int n     = layer ? N_DST1 : N_DST0;
    int* __restrict__ cnt    = layer ? g_cnt1    : g_cnt0;
    int* __restrict__ rowptr = layer ? g_rowptr1 : g_rowptr0;
    int* __restrict__ cursor = layer ? g_cursor1 : g_cursor0;

    __shared__ int wsum[32];
    __shared__ int carry_s;
    const int tid  = threadIdx.x;
    const int lane = tid & 31;
    const int wid  = tid >> 5;
    if (tid == 0) carry_s = 0;
    __syncthreads();

    for (int base = 0; base < n; base += 8192) {
        int i0 = base + tid * 8;
        int v[8];
        if (i0 + 8 <= n) {
            int4 a = *(const int4*)&cnt[i0];
            int4 b = *(const int4*)&cnt[i0 + 4];
            v[0] = a.x; v[1] = a.y; v[2] = a.z; v[3] = a.w;
            v[4] = b.x; v[5] = b.y; v[6] = b.z; v[7] = b.w;
        } else {
#pragma unroll
            for (int j = 0; j < 8; j++) v[j] = (i0 + j < n) ? cnt[i0 + j] : 0;
        }
        int incl[8];
        int s = 0;
#pragma unroll
        for (int j = 0; j < 8; j++) { s += v[j]; incl[j] = s; }
        const int tot = s;
        int ws = tot;
#pragma unroll
        for (int off = 1; off < 32; off <<= 1) {
            int t = __shfl_up_sync(0xffffffffu, ws, off);
            if (lane >= off) ws += t;
        }
        if (lane == 31) wsum[wid] = ws;
        __syncthreads();
        if (wid == 0) {
            int w2 = wsum[lane];
#pragma unroll
            for (int off = 1; off < 32; off <<= 1) {
                int t = __shfl_up_sync(0xffffffffu, w2, off);
                if (lane >= off) w2 += t;
            }
            wsum[lane] = w2;
        }
        __syncthreads();
        int off0 = carry_s + ((wid > 0) ? wsum[wid - 1] : 0) + (ws - tot);
        if (i0 + 8 <= n) {
            int4 r0, r1;
            r0.x = off0 + incl[0] - v[0]; r0.y = off0 + incl[1] - v[1];
            r0.z = off0 + incl[2] - v[2]; r0.w = off0 + incl[3] - v[3];
            r1.x = off0 + incl[4] - v[4]; r1.y = off0 + incl[5] - v[5];
            r1.z = off0 + incl[6] - v[6]; r1.w = off0 + incl[7] - v[7];
            *(int4*)&rowptr[i0] = r0; *(int4*)&rowptr[i0 + 4] = r1;
            *(int4*)&cursor[i0] = r0; *(int4*)&cursor[i0 + 4] = r1;
        } else {
#pragma unroll
            for (int j = 0; j < 8; j++)
                if (i0 + j < n) {
                    int e = off0 + incl[j] - v[j];
                    rowptr[i0 + j] = e; cursor[i0 + j] = e;
                }
        }
        __syncthreads();
        if (tid == 0) carry_s += wsum[31];
        __syncthreads();
    }
    if (tid == 0) rowptr[n] = carry_s;
}

// ---------------- CSR build: fused fill (both layers), 4 edges/thread ---------
__global__ void fill2_kernel(const int* __restrict__ ei0,
                             const int* __restrict__ ei1) {
    const int Q0 = NEDGE0 / 4, Q1 = NEDGE1 / 4;
    int t = blockIdx.x * blockDim.x + threadIdx.x;
    if (t < Q0) {
        int4 s = ((const int4*)ei0)[t];
        int4 d = ((const int4*)(ei0 + NEDGE0))[t];
        g_col0[atomicAdd(&g_cursor0[d.x], 1)] = s.x;
        g_col0[atomicAdd(&g_cursor0[d.y], 1)] = s.y;
        g_col0[atomicAdd(&g_cursor0[d.z], 1)] = s.z;
        g_col0[atomicAdd(&g_cursor0[d.w], 1)] = s.w;
    } else if (t < Q0 + Q1) {
        int4 s = ((const int4*)ei1)[t - Q0];
        int4 d = ((const int4*)(ei1 + NEDGE1))[t - Q0];
        g_col1[atomicAdd(&g_cursor1[d.x], 1)] = s.x;
        g_col1[atomicAdd(&g_cursor1[d.y], 1)] = s.y;
        g_col1[atomicAdd(&g_cursor1[d.z], 1)] = s.z;
        g_col1[atomicAdd(&g_cursor1[d.w], 1)] = s.w;
    }
}

// ---------------- dst-major aggregation (mean), no float atomics --------------
__global__ void agg0_kernel(const float* __restrict__ x) {
    int w = (blockIdx.x * blockDim.x + threadIdx.x) >> 5;
    int lane = threadIdx.x & 31;
    if (w >= N_DST0) return;
    int beg = g_rowptr0[w], end = g_rowptr0[w + 1];
    float4 a0 = make_float4(0.f, 0.f, 0.f, 0.f);
    float4 a1 = a0, a2 = a0, a3 = a0;
    int e = beg;
    for (; e + 4 <= end; e += 4) {
        int s0 = g_col0[e], s1 = g_col0[e + 1], s2 = g_col0[e + 2], s3 = g_col0[e + 3];
        float4 v0 = ((const float4*)(x + (size_t)s0 * D_IN))[lane];
        float4 v1 = ((const float4*)(x + (size_t)s1 * D_IN))[lane];
        float4 v2 = ((const float4*)(x + (size_t)s2 * D_IN))[lane];
        float4 v3 = ((const float4*)(x + (size_t)s3 * D_IN))[lane];
        a0.x += v0.x; a0.y += v0.y; a0.z += v0.z; a0.w += v0.w;
        a1.x += v1.x; a1.y += v1.y; a1.z += v1.z; a1.w += v1.w;
        a2.x += v2.x; a2.y += v2.y; a2.z += v2.z; a2.w += v2.w;
        a3.x += v3.x; a3.y += v3.y; a3.z += v3.z; a3.w += v3.w;
    }
    for (; e < end; e++) {
        float4 v = ((const float4*)(x + (size_t)g_col0[e] * D_IN))[lane];
        a0.x += v.x; a0.y += v.y; a0.z += v.z; a0.w += v.w;
    }
    a0.x += a1.x + a2.x + a3.x;
    a0.y += a1.y + a2.y + a3.y;
    a0.z += a1.z + a2.z + a3.z;
    a0.w += a1.w + a2.w + a3.w;
    float s = 1.f / fmaxf((float)(end - beg), 1.f);
    a0.x *= s; a0.y *= s; a0.z *= s; a0.w *= s;
    ((float4*)(g_mean0 + (size_t)w * D_IN))[lane] = a0;
}

__global__ void agg1_kernel() {
    int w = (blockIdx.x * blockDim.x + threadIdx.x) >> 5;
    int lane = threadIdx.x & 31;
    if (w >= N_DST1) return;
    int beg = g_rowptr1[w], end = g_rowptr1[w + 1];
    float4 a0 = make_float4(0.f, 0.f, 0.f, 0.f);
    float4 a1 = a0, b0 = a0, b1 = a0;
    int e = beg;
    for (; e + 2 <= end; e += 2) {
        const float4* h0 = (const float4*)(g_h + (size_t)g_col1[e] * D_H);
        const float4* h1 = (const float4*)(g_h + (size_t)g_col1[e + 1] * D_H);
        float4 u0 = h0[lane], u1 = h0[lane + 32];
        float4 w0 = h1[lane], w1 = h1[lane + 32];
        a0.x += u0.x; a0.y += u0.y; a0.z += u0.z; a0.w += u0.w;
        a1.x += u1.x; a1.y += u1.y; a1.z += u1.z; a1.w += u1.w;
        b0.x += w0.x; b0.y += w0.y; b0.z += w0.z; b0.w += w0.w;
        b1.x += w1.x; b1.y += w1.y; b1.z += w1.z; b1.w += w1.w;
    }
    if (e < end) {
        const float4* h0 = (const float4*)(g_h + (size_t)g_col1[e] * D_H);
        float4 u0 = h0[lane], u1 = h0[lane + 32];
        a0.x += u0.x; a0.y += u0.y; a0.z += u0.z; a0.w += u0.w;
        a1.x += u1.x; a1.y += u1.y; a1.z += u1.z; a1.w += u1.w;
    }
    a0.x += b0.x; a0.y += b0.y; a0.z += b0.z; a0.w += b0.w;
    a1.x += b1.x; a1.y += b1.y; a1.z += b1.z; a1.w += b1.w;
    float s = 1.f / fmaxf((float)(end - beg), 1.f);
    a0.x *= s; a0.y *= s; a0.z *= s; a0.w *= s;
    a1.x *= s; a1.y *= s; a1.z *= s; a1.w *= s;
    float4* op = (float4*)(g_mean1 + (size_t)w * D_H);
    op[lane] = a0;
    op[lane + 32] = a1;
}

// ---------------- TF32 tensor-core dual-A GEMM --------------------------------
#define BM 128
#define BN 128
#define BK 16
#define AS_STRIDE 20    // conflict-free A fragment reads
#define BS_STRIDE 136   // conflict-free B fragment reads

__device__ __forceinline__ uint32_t f2tf32(float f) {
    uint32_t u;
    asm("cvt.rna.tf32.f32 %0, %1;" : "=r"(u) : "f"(f));
    return u;
}

__global__ void __launch_bounds__(256, 2)
gemm_dual_tf32_kernel(const float* __restrict__ A1,
                      const float* __restrict__ A2,
                      const float* __restrict__ W1, const float* __restrict__ W2,
                      const float* __restrict__ bias,
                      float* __restrict__ out, int M, int K, int do_relu) {
    __shared__ uint32_t As[BM * AS_STRIDE];   // [m][k] tf32 bits
    __shared__ uint32_t Bs[BK * BS_STRIDE];   // [k][n] tf32 bits

    const int tid  = threadIdx.x;
    const int lane = tid & 31;
    const int wrp  = tid >> 5;
    const int m_warp = (wrp & 1) * 64;
    const int n_warp = (wrp >> 1) * 32;
    const int bm = blockIdx.y * BM;
    const int bn = blockIdx.x * BN;

    const int a_r  = tid >> 2;
    const int a_kc = (tid & 3) * 4;
    const int b_kr = tid >> 5;
    const int b_c  = (tid & 31) * 4;

    float acc[4][4][4];
#pragma unroll
    for (int i = 0; i < 4; i++)
#pragma unroll
        for (int j = 0; j < 4; j++)
#pragma unroll
            for (int r = 0; r < 4; r++) acc[i][j][r] = 0.f;

    const int fr = lane >> 2;
    const int fc = lane & 3;

    for (int pass = 0; pass < 2; pass++) {
        const float* __restrict__ A = pass ? A2 : A1;
        const float* __restrict__ W = pass ? W2 : W1;
        const int gr0 = bm + a_r;
        const int gr1 = gr0 + 64;

        for (int k0 = 0; k0 < K; k0 += BK) {
            float4 av0 = make_float4(0.f, 0.f, 0.f, 0.f);
            float4 av1 = av0;
            if (gr0 < M) av0 = *(const float4*)&A[(size_t)gr0 * K + k0 + a_kc];
            if (gr1 < M) av1 = *(const float4*)&A[(size_t)gr1 * K + k0 + a_kc];
            float4 bv0 = *(const float4*)&W[(size_t)(k0 + b_kr) * D_H + bn + b_c];
            float4 bv1 = *(const float4*)&W[(size_t)(k0 + b_kr + 8) * D_H + bn + b_c];
            __syncthreads();
            {
                uint32_t* p0 = &As[a_r * AS_STRIDE + a_kc];
                p0[0] = f2tf32(av0.x); p0[1] = f2tf32(av0.y);
                p0[2] = f2tf32(av0.z); p0[3] = f2tf32(av0.w);
                uint32_t* p1 = &As[(a_r + 64) * AS_STRIDE + a_kc];
                p1[0] = f2tf32(av1.x); p1[1] = f2tf32(av1.y);
                p1[2] = f2tf32(av1.z); p1[3] = f2tf32(av1.w);
                uint32_t* q0 = &Bs[b_kr * BS_STRIDE + b_c];
                q0[0] = f2tf32(bv0.x); q0[1] = f2tf32(bv0.y);
                q0[2] = f2tf32(bv0.z); q0[3] = f2tf32(bv0.w);
                uint32_t* q1 = &Bs[(b_kr + 8) * BS_STRIDE + b_c];
                q1[0] = f2tf32(bv1.x); q1[1] = f2tf32(bv1.y);
                q1[2] = f2tf32(bv1.z); q1[3] = f2tf32(bv1.w);
            }
            __syncthreads();

#pragma unroll
            for (int ks = 0; ks < BK; ks += 8) {
                uint32_t af[4][4];
#pragma unroll
                for (int mt = 0; mt < 4; mt++) {
                    int rb = m_warp + mt * 16 + fr;
                    af[mt][0] = As[rb * AS_STRIDE + ks + fc];
                    af[mt][1] = As[(rb + 8) * AS_STRIDE + ks + fc];
                    af[mt][2] = As[rb * AS_STRIDE + ks + fc + 4];
                    af[mt][3] = As[(rb + 8) * AS_STRIDE + ks + fc + 4];
                }
                uint32_t bf[4][2];
#pragma unroll
                for (int nt = 0; nt < 4; nt++) {
                    int nb = n_warp + nt * 8 + fr;
                    bf[nt][0] = Bs[(ks + fc) * BS_STRIDE + nb];
                    bf[nt][1] = Bs[(ks + fc + 4) * BS_STRIDE + nb];
                }
#pragma unroll
                for (int mt = 0; mt < 4; mt++)
#pragma unroll
                    for (int nt = 0; nt < 4; nt++) {
                        asm volatile(
                            "mma.sync.aligned.m16n8k8.row.col.f32.tf32.tf32.f32 "
                            "{%0,%1,%2,%3}, {%4,%5,%6,%7}, {%8,%9}, {%0,%1,%2,%3};"
                            : "+f"(acc[mt][nt][0]), "+f"(acc[mt][nt][1]),
                              "+f"(acc[mt][nt][2]), "+f"(acc[mt][nt][3])
                            : "r"(af[mt][0]), "r"(af[mt][1]),
                              "r"(af[mt][2]), "r"(af[mt][3]),
                              "r"(bf[nt][0]), "r"(bf[nt][1]));
                    }
            }
        }
    }

#pragma unroll
    for (int mt = 0; mt < 4; mt++) {
#pragma unroll
        for (int nt = 0; nt < 4; nt++) {
            int col = bn + n_warp + nt * 8 + fc * 2;
            float b0 = bias[col], b1 = bias[col + 1];
            int r0 = bm + m_warp + mt * 16 + fr;
            int r1 = r0 + 8;
            float v0 = acc[mt][nt][0] + b0, v1 = acc[mt][nt][1] + b1;
            float v2 = acc[mt][nt][2] + b0, v3 = acc[mt][nt][3] + b1;
            if (do_relu) {
                v0 = fmaxf(v0, 0.f); v1 = fmaxf(v1, 0.f);
                v2 = fmaxf(v2, 0.f); v3 = fmaxf(v3, 0.f);
            }
            if (r0 < M) *(float2*)&out[(size_t)r0 * D_H + col] = make_float2(v0, v1);
            if (r1 < M) *(float2*)&out[(size_t)r1 * D_H + col] = make_float2(v2, v3);
        }
    }
}

// ---------------- epilogue: copy raw out + log_softmax ------------------------
__global__ void emit_kernel(const float* __restrict__ in,
                            float* __restrict__ out_raw,
                            float* __restrict__ out_ls) {
    int row = blockIdx.x;
    int t = threadIdx.x;
    float v = in[row * D_H + t];
    __shared__ float red[D_H];
    red[t] = v;
    __syncthreads();
#pragma unroll
    for (int s = 128; s > 0; s >>= 1) {
        if (t < s) red[t] = fmaxf(red[t], red[t + s]);
        __syncthreads();
    }
    float m = red[0];
    __syncthreads();
    float e = expf(v - m);
    red[t] = e;
    __syncthreads();
#pragma unroll
    for (int s = 128; s > 0; s >>= 1) {
        if (t < s) red[t] += red[t + s];
        __syncthreads();
    }
    float ls = v - m - logf(red[0]);
    if (out_raw) out_raw[row * D_H + t] = v;
    out_ls[row * D_H + t] = ls;
}

// ---------------- launch ------------------------------------------------------
extern "C" void kernel_launch(void* const* d_in, const int* in_sizes, int n_in,
                              void* d_out, int out_size) {
    const float* x     = (const float*)d_in[0];
    const int* ei0     = (const int*)d_in[1];
    const int* ei1     = (const int*)d_in[2];
    const float* W_l0  = (const float*)d_in[3];
    const float* b_l0  = (const float*)d_in[4];
    const float* W_r0  = (const float*)d_in[5];
    const float* W_l1  = (const float*)d_in[6];
    const float* b_l1  = (const float*)d_in[7];
    const float* W_r1  = (const float*)d_in[8];
    float* out         = (float*)d_out;

    float *p_mean0, *p_h, *p_mean1, *p_out;
    int *p_cnt0, *p_cnt1;
    cudaGetSymbolAddress((void**)&p_mean0, g_mean0);
    cudaGetSymbolAddress((void**)&p_h,     g_h);
    cudaGetSymbolAddress((void**)&p_mean1, g_mean1);
    cudaGetSymbolAddress((void**)&p_out,   g_out);
    cudaGetSymbolAddress((void**)&p_cnt0,  g_cnt0);
    cudaGetSymbolAddress((void**)&p_cnt1,  g_cnt1);

    // CSR build (both layers fused per stage); counts zeroed via memset nodes
    cudaMemsetAsync(p_cnt0, 0, N_DST0 * sizeof(int), 0);
    cudaMemsetAsync(p_cnt1, 0, N_DST1 * sizeof(int), 0);
    const int QTOT = NEDGE0 / 4 + NEDGE1 / 4;   // 150000 threads
    count2_kernel<<<(QTOT + 255) / 256, 256>>>(ei0, ei1);
    scan2_kernel<<<2, 1024>>>();
    fill2_kernel<<<(QTOT + 255) / 256, 256>>>(ei0, ei1);

    // layer 0: h = relu(mean0 @ W_l0 + b_l0 + x[:20000] @ W_r0)
    agg0_kernel<<<(N_DST0 * 32 + 255) / 256, 256>>>(x);
    gemm_dual_tf32_kernel<<<dim3(D_H / BN, (N_DST0 + BM - 1) / BM), 256>>>(
        p_mean0, x, W_l0, W_r0, b_l0, p_h, N_DST0, D_IN, 1);

    // layer 1: out = mean1 @ W_l1 + b_l1 + h[:4000] @ W_r1
    agg1_kernel<<<(N_DST1 * 32 + 255) / 256, 256>>>();
    gemm_dual_tf32_kernel<<<dim3(D_H / BN, (N_DST1 + BM - 1) / BM), 256>>>(
        p_mean1, p_h, W_l1, W_r1, b_l1, p_out, N_DST1, D_H, 0);

    // emit: reference returns (out, log_softmax(out)) -> concatenated if room
    const int NM = N_DST1 * D_H;
    float* out_raw = (out_size >= 2 * NM) ? out : nullptr;
    float* out_ls  = (out_size >= 2 * NM) ? out + NM : out;
    emit_kernel<<<N_DST1, D_H>>>(p_out, out_raw, out_ls);
}